// round 16
// baseline (speedup 1.0000x reference)
#include <cuda_runtime.h>
#include <cuda_bf16.h>

typedef unsigned int u32;
typedef unsigned long long u64;

#define NB     4
#define QLEN   4096
#define KLEN   4096
#define VH     64
#define TQ     128
#define TK     32
#define NT     256
#define NTILES 128          // KLEN / TK

#define PQ  144             // Q/K plane row pitch bytes (64 bf16 + 8 pad)
#define PVR 80              // V plane row pitch bytes (32 keys bf16 + 16 pad)

#define QPLANE 18432        // 128 x 144
#define KPLANE 4608         // 32 x 144
#define VPLANE 5120         // 64 x 80
#define KTILE  27648        // 6 planes (KrH,KrL,KiH,KiL,KdH,KdL)
#define VTILE  30720        // 6 planes (VrH,VrL,ViH,ViL,VsH,VsL)

// ---- smem byte offsets ----
#define SM_Q    0           // 6 planes: QrH,QrL,QiH,QiL,QsH,QsL
#define SM_K0   110592
#define SM_K1   138240
#define SM_V0   165888
#define SM_V1   196608
#define SM_TOTAL 227328

__device__ static __align__(16) unsigned char g_kpre[(size_t)NB * NTILES * KTILE];
__device__ static __align__(16) unsigned char g_vpre[(size_t)NB * NTILES * VTILE];

#define LDSM4(R, addr) \
    asm volatile("ldmatrix.sync.aligned.m8n8.x4.shared.b16 {%0,%1,%2,%3}, [%4];" \
        : "=r"((R)[0]), "=r"((R)[1]), "=r"((R)[2]), "=r"((R)[3]) : "r"(addr))

#define MMA(D, A, B0, B1) \
    asm volatile("mma.sync.aligned.m16n8k16.row.col.f32.bf16.bf16.f32 " \
        "{%0,%1,%2,%3}, {%4,%5,%6,%7}, {%8,%9}, {%0,%1,%2,%3};" \
        : "+f"((D)[0]), "+f"((D)[1]), "+f"((D)[2]), "+f"((D)[3]) \
        : "r"((A)[0]), "r"((A)[1]), "r"((A)[2]), "r"((A)[3]), "r"(B0), "r"(B1))

#define CP16(dst, src) \
    asm volatile("cp.async.cg.shared.global [%0], [%1], 16;" \
        :: "r"(dst), "l"(src) : "memory")
#define CP_COMMIT() asm volatile("cp.async.commit_group;" ::: "memory")
#define CP_WAIT0()  asm volatile("cp.async.wait_group 0;"  ::: "memory")

__device__ __forceinline__ u32 smem_u32(const void* p) {
    u32 a;
    asm("{ .reg .u64 t; cvta.to.shared.u64 t, %1; cvt.u32.u64 %0, t; }"
        : "=r"(a) : "l"(p));
    return a;
}
__device__ __forceinline__ void split2(float a, float b, u32& hp, u32& lp) {
    __nv_bfloat16 ha = __float2bfloat16(a), hb = __float2bfloat16(b);
    float la = a - __bfloat162float(ha), lb = b - __bfloat162float(hb);
    __nv_bfloat16 lA = __float2bfloat16(la), lB = __float2bfloat16(lb);
    hp = (u32)__bfloat16_as_ushort(ha) | ((u32)__bfloat16_as_ushort(hb) << 16);
    lp = (u32)__bfloat16_as_ushort(lA) | ((u32)__bfloat16_as_ushort(lB) << 16);
}

// ---- prep: K -> planar {Kr, Ki, Kd=Ki-Kr} hi/lo planes (rows=key, cols=64 d) ----
__global__ void prep_k_kernel(const float* __restrict__ gk) {
    int g = blockIdx.x * 8 + (threadIdx.x >> 5);    // global k-row (b*4096+krow)
    int lane = threadIdx.x & 31;
    int b = g >> 12, krow = g & 4095;
    int tile = krow >> 5, r = krow & 31;
    float4 v = ((const float4*)gk)[(size_t)g * 32 + lane];  // d=2lane: (Kr,Ki,Kr',Ki')
    unsigned char* base = g_kpre + (size_t)(b * NTILES + tile) * KTILE
                        + r * PQ + lane * 4;
    u32 hp, lp;
    split2(v.x, v.z, hp, lp);                 // Kr
    *(u32*)(base        ) = hp;  *(u32*)(base +  4608) = lp;
    split2(v.y, v.w, hp, lp);                 // Ki
    *(u32*)(base +  9216) = hp;  *(u32*)(base + 13824) = lp;
    split2(v.y - v.x, v.w - v.z, hp, lp);     // Kd = Ki - Kr
    *(u32*)(base + 18432) = hp;  *(u32*)(base + 23040) = lp;
}

// ---- prep: V -> planar transposed {Vr, Vi, Vs=Vr+Vi} hi/lo (rows=v-col, cols=32 keys) ----
__global__ void prep_v_kernel(const float* __restrict__ gv) {
    int bt = blockIdx.x;                            // b*128 + tile
    int b = bt >> 7, tile = bt & 127;
    int t = threadIdx.x;
    int v = t & 63;
    int kb = (t >> 6) * 8;                          // 0,8,16,24
    const float2* src = (const float2*)gv
        + ((size_t)(b * KLEN + tile * TK + kb) * VH + v);
    unsigned char* base = g_vpre + (size_t)bt * VTILE + v * PVR + kb * 2;
    u32 rh[4], rl[4], ih[4], il[4], sh[4], sl[4];
    #pragma unroll
    for (int j = 0; j < 4; ++j) {
        float2 x0 = src[(size_t)(2 * j) * VH];
        float2 x1 = src[(size_t)(2 * j + 1) * VH];
        split2(x0.x, x1.x, rh[j], rl[j]);
        split2(x0.y, x1.y, ih[j], il[j]);
        split2(x0.x + x0.y, x1.x + x1.y, sh[j], sl[j]);
    }
    *(uint4*)(base         ) = make_uint4(rh[0], rh[1], rh[2], rh[3]);
    *(uint4*)(base +  5120) = make_uint4(rl[0], rl[1], rl[2], rl[3]);
    *(uint4*)(base + 10240) = make_uint4(ih[0], ih[1], ih[2], ih[3]);
    *(uint4*)(base + 15360) = make_uint4(il[0], il[1], il[2], il[3]);
    *(uint4*)(base + 20480) = make_uint4(sh[0], sh[1], sh[2], sh[3]);
    *(uint4*)(base + 25600) = make_uint4(sl[0], sl[1], sl[2], sl[3]);
}

__device__ __forceinline__ void issue_k(u32 smb, int b, int t, int buf) {
    const unsigned char* src = g_kpre + (size_t)(b * NTILES + t) * KTILE;
    u32 dst = smb + SM_K0 + buf * (SM_K1 - SM_K0);
    #pragma unroll 2
    for (int i = threadIdx.x; i < KTILE / 16; i += NT)
        CP16(dst + i * 16, src + (size_t)i * 16);
}
__device__ __forceinline__ void issue_v(u32 smb, int b, int t, int buf) {
    const unsigned char* src = g_vpre + (size_t)(b * NTILES + t) * VTILE;
    u32 dst = smb + SM_V0 + buf * (SM_V1 - SM_V0);
    #pragma unroll 2
    for (int i = threadIdx.x; i < VTILE / 16; i += NT)
        CP16(dst + i * 16, src + (size_t)i * 16);
}

__global__ __launch_bounds__(NT, 1)
void cdpa_mma_kernel(const float* __restrict__ gq,
                     float* __restrict__ gout)
{
    extern __shared__ char sm[];
    const u32 smb = smem_u32(sm);
    const int tid = threadIdx.x;
    const int lane = tid & 31, wid = tid >> 5;      // 8 warps = 8 q-slices of 16
    const int g = lane >> 2, tg = lane & 3;
    const int b = blockIdx.y, q0 = blockIdx.x * TQ;

    issue_k(smb, b, 0, 0);
    issue_v(smb, b, 0, 0);
    CP_COMMIT();

    // ldmatrix lane addressing
    const int arow = lane & 15, akb = lane >> 4;
    const int bn = (lane & 7) + ((lane >> 4) << 3), bkb = (lane >> 3) & 1;

    const u32 aQ  = smb + SM_Q + (u32)(16 * wid + arow) * PQ + akb * 16;
    const u32 kfo = (u32)bn * PQ + bkb * 16;    // + nblk*16*PQ + ks*32 (+ plane)
    const u32 vfo = (u32)bn * PVR + bkb * 16;   // + nblk*16*PVR + 32*c (+ plane)

    // ---- Q planes: Qr, Qi, Qs (scaled 1/8), bf16 hi/lo ----
    {
        const float4* gqp = (const float4*)gq + (size_t)(b * QLEN + q0) * 32;
        #pragma unroll 4
        for (int it = 0; it < 16; ++it) {
            int e = it * NT + tid;
            int row = e >> 5, c4 = e & 31;      // c4 = d-pair (2c4, 2c4+1)
            float4 v = gqp[e];
            v.x *= 0.125f; v.y *= 0.125f; v.z *= 0.125f; v.w *= 0.125f;
            u32 off = (u32)row * PQ + c4 * 4;
            u32 hp, lp;
            split2(v.x, v.z, hp, lp);           // Qr
            *(u32*)(sm + off            ) = hp;
            *(u32*)(sm + off +   QPLANE ) = lp;
            split2(v.y, v.w, hp, lp);           // Qi
            *(u32*)(sm + off + 2*QPLANE ) = hp;
            *(u32*)(sm + off + 3*QPLANE ) = lp;
            split2(v.x + v.y, v.z + v.w, hp, lp);   // Qs
            *(u32*)(sm + off + 4*QPLANE ) = hp;
            *(u32*)(sm + off + 5*QPLANE ) = lp;
        }
    }

    float Ty1[8][4], Ty2[8][4], Ty3[8][4], Zp[2];
    Zp[0] = 0.0f; Zp[1] = 0.0f;
    #pragma unroll
    for (int nf = 0; nf < 8; ++nf)
        #pragma unroll
        for (int e = 0; e < 4; ++e) { Ty1[nf][e] = 0.0f; Ty2[nf][e] = 0.0f; Ty3[nf][e] = 0.0f; }

    for (int t = 0; t < NTILES; ++t) {
        CP_WAIT0();
        __syncthreads();        // K[t],V[t] visible; alt buffers fully consumed

        if (t + 1 < NTILES) {
            issue_k(smb, b, t + 1, (t + 1) & 1);
            issue_v(smb, b, t + 1, (t + 1) & 1);
            CP_COMMIT();
        }
        const u32 kb = smb + SM_K0 + (u32)(t & 1) * (SM_K1 - SM_K0);
        const u32 vb = smb + SM_V0 + (u32)(t & 1) * (SM_V1 - SM_V0);

        // ---- S gemm (Karatsuba): T1=Qr.Kr, T2=Qi.Ki, T3=Qs.Kd; planar K=64 ----
        float t1[4][4], t2[4][4], t3[4][4];
        #pragma unroll
        for (int nf = 0; nf < 4; ++nf)
            #pragma unroll
            for (int e = 0; e < 4; ++e) { t1[nf][e] = 0.0f; t2[nf][e] = 0.0f; t3[nf][e] = 0.0f; }

        #pragma unroll
        for (int ks = 0; ks < 4; ++ks) {
            const u32 ko = ks * 32;
            u32 qrh[4], qrl[4], qih[4], qil[4], qsh[4], qsl[4];
            LDSM4(qrh, aQ + ko);
            LDSM4(qrl, aQ + QPLANE + ko);
            LDSM4(qih, aQ + 2*QPLANE + ko);
            LDSM4(qil, aQ + 3*QPLANE + ko);
            LDSM4(qsh, aQ + 4*QPLANE + ko);
            LDSM4(qsl, aQ + 5*QPLANE + ko);
            #pragma unroll
            for (int nblk = 0; nblk < 2; ++nblk) {
                const u32 base = kb + kfo + (u32)nblk * (16 * PQ) + ko;
                u32 krh[4], krl[4], kih[4], kil[4], kdh[4], kdl[4];
                LDSM4(krh, base);          LDSM4(krl, base +  4608);
                LDSM4(kih, base +  9216);  LDSM4(kil, base + 13824);
                LDSM4(kdh, base + 18432);  LDSM4(kdl, base + 23040);
                #pragma unroll
                for (int h = 0; h < 2; ++h) {
                    const int nf = 2 * nblk + h;
                    MMA(t1[nf], qrh, krh[2*h], krh[2*h+1]);
                    MMA(t1[nf], qrh, krl[2*h], krl[2*h+1]);
                    MMA(t1[nf], qrl, krh[2*h], krh[2*h+1]);
                    MMA(t2[nf], qih, kih[2*h], kih[2*h+1]);
                    MMA(t2[nf], qih, kil[2*h], kil[2*h+1]);
                    MMA(t2[nf], qil, kih[2*h], kih[2*h+1]);
                    MMA(t3[nf], qsh, kdh[2*h], kdh[2*h+1]);
                    MMA(t3[nf], qsh, kdl[2*h], kdl[2*h+1]);
                    MMA(t3[nf], qsl, kdh[2*h], kdh[2*h+1]);
                }
            }
        }

        // ---- epilogue: Sr=T1+T2, Si=T3+T1-T2; n=|S|, e=exp(n), A=S*e/n ----
        // reuse t1 <- Ar, t2 <- Ai, t3 <- As=Ar+Ai
        #pragma unroll
        for (int nf = 0; nf < 4; ++nf) {
            #pragma unroll
            for (int e = 0; e < 4; ++e) {
                float a = t1[nf][e] + t2[nf][e];
                float bb = t3[nf][e] + t1[nf][e] - t2[nf][e];
                float s2 = a * a + bb * bb;
                float r = rsqrtf(s2);
                float n = s2 * r;
                float ee = __expf(n);
                float w = ee * r;
                if (s2 < 1e-30f) { w = 0.0f; ee = 1.0f; }
                Zp[e >> 1] += ee;
                float Ar = a * w, Ai = bb * w;
                t1[nf][e] = Ar;
                t2[nf][e] = Ai;
                t3[nf][e] = Ar + Ai;
            }
        }

        // ---- AV gemm (Karatsuba): Ty1+=Ar.Vr, Ty2+=Ai.Vi, Ty3+=As.Vs ----
        #pragma unroll
        for (int c = 0; c < 2; ++c) {
            u32 ArH[4], ArL[4], AiH[4], AiL[4], AsH[4], AsL[4];
            split2(t1[2*c][0],   t1[2*c][1],   ArH[0], ArL[0]);
            split2(t1[2*c][2],   t1[2*c][3],   ArH[1], ArL[1]);
            split2(t1[2*c+1][0], t1[2*c+1][1], ArH[2], ArL[2]);
            split2(t1[2*c+1][2], t1[2*c+1][3], ArH[3], ArL[3]);
            split2(t2[2*c][0],   t2[2*c][1],   AiH[0], AiL[0]);
            split2(t2[2*c][2],   t2[2*c][3],   AiH[1], AiL[1]);
            split2(t2[2*c+1][0], t2[2*c+1][1], AiH[2], AiL[2]);
            split2(t2[2*c+1][2], t2[2*c+1][3], AiH[3], AiL[3]);
            split2(t3[2*c][0],   t3[2*c][1],   AsH[0], AsL[0]);
            split2(t3[2*c][2],   t3[2*c][3],   AsH[1], AsL[1]);
            split2(t3[2*c+1][0], t3[2*c+1][1], AsH[2], AsL[2]);
            split2(t3[2*c+1][2], t3[2*c+1][3], AsH[3], AsL[3]);

            // Vr -> Ty1 (with Ar)
            #pragma unroll
            for (int nblk = 0; nblk < 4; ++nblk) {
                const u32 o2 = vfo + (u32)nblk * (16 * PVR) + 32 * c;
                u32 vh[4], vl[4];
                LDSM4(vh, vb + o2); LDSM4(vl, vb + 5120 + o2);
                #pragma unroll
                for (int h = 0; h < 2; ++h) {
                    const int nf = 2 * nblk + h;
                    MMA(Ty1[nf], ArH, vh[2*h], vh[2*h+1]);
                    MMA(Ty1[nf], ArH, vl[2*h], vl[2*h+1]);
                    MMA(Ty1[nf], ArL, vh[2*h], vh[2*h+1]);
                }
            }
            // Vi -> Ty2 (with Ai)
            #pragma unroll
            for (int nblk = 0; nblk < 4; ++nblk) {
                const u32 o2 = vfo + (u32)nblk * (16 * PVR) + 32 * c;
                u32 vh[4], vl[4];
                LDSM4(vh, vb + 10240 + o2); LDSM4(vl, vb + 15360 + o2);
                #pragma unroll
                for (int h = 0; h < 2; ++h) {
                    const int nf = 2 * nblk + h;
                    MMA(Ty2[nf], AiH, vh[2*h], vh[2*h+1]);
                    MMA(Ty2[nf], AiH, vl[2*h], vl[2*h+1]);
                    MMA(Ty2[nf], AiL, vh[2*h], vh[2*h+1]);
                }
            }
            // Vs -> Ty3 (with As)
            #pragma unroll
            for (int nblk = 0; nblk < 4; ++nblk) {
                const u32 o2 = vfo + (u32)nblk * (16 * PVR) + 32 * c;
                u32 vh[4], vl[4];
                LDSM4(vh, vb + 20480 + o2); LDSM4(vl, vb + 25600 + o2);
                #pragma unroll
                for (int h = 0; h < 2; ++h) {
                    const int nf = 2 * nblk + h;
                    MMA(Ty3[nf], AsH, vh[2*h], vh[2*h+1]);
                    MMA(Ty3[nf], AsH, vl[2*h], vl[2*h+1]);
                    MMA(Ty3[nf], AsL, vh[2*h], vh[2*h+1]);
                }
            }
        }
    }

    // ---- Z reduce within quad ----
    #pragma unroll
    for (int rr = 0; rr < 2; ++rr) {
        float z = Zp[rr];
        z += __shfl_xor_sync(0xffffffffu, z, 1);
        z += __shfl_xor_sync(0xffffffffu, z, 2);
        Zp[rr] = z;
    }

    // ---- output: Yr=T1-T2, Yi=T3-T1-T2, /Z -> [B, Q, V, 2] ----
    #pragma unroll
    for (int rr = 0; rr < 2; ++rr) {
        const float inv = 1.0f / Zp[rr];
        const int qrow = q0 + 16 * wid + g + 8 * rr;
        float2* o = (float2*)gout + (size_t)(b * QLEN + qrow) * VH;
        #pragma unroll
        for (int nf = 0; nf < 8; ++nf) {
            #pragma unroll
            for (int cc = 0; cc < 2; ++cc) {
                const int e = 2 * rr + cc;
                const int v = 8 * nf + 2 * tg + cc;
                float yr = Ty1[nf][e] - Ty2[nf][e];
                float yi = Ty3[nf][e] - Ty1[nf][e] - Ty2[nf][e];
                o[v] = make_float2(yr * inv, yi * inv);
            }
        }
    }
}

extern "C" void kernel_launch(void* const* d_in, const int* in_sizes, int n_in,
                              void* d_out, int out_size)
{
    const float* q = (const float*)d_in[0];
    const float* k = (const float*)d_in[1];
    const float* v = (const float*)d_in[2];
    float* out = (float*)d_out;

    prep_k_kernel<<<2048, 256>>>(k);
    prep_v_kernel<<<512, 256>>>(v);

    cudaFuncSetAttribute(cdpa_mma_kernel,
                         cudaFuncAttributeMaxDynamicSharedMemorySize, SM_TOTAL);
    dim3 grid(QLEN / TQ, NB);
    cdpa_mma_kernel<<<grid, NT, SM_TOTAL>>>(q, out);
}

// round 17
// speedup vs baseline: 1.4424x; 1.4424x over previous
#include <cuda_runtime.h>
#include <cuda_bf16.h>

typedef unsigned int u32;
typedef unsigned long long u64;

#define NB     4
#define QLEN   4096
#define KLEN   4096
#define VH     64
#define TQ     64
#define TK     32
#define NT     128
#define NTILES 128          // KLEN / TK

#define PK 272              // K/Q tile row pitch bytes (128 bf16 + 16 pad)
#define PVR 80              // V plane row pitch bytes (32 keys bf16 + 16 pad)

#define KTILE 34816         // 4 planes x 32 x 272
#define VTILE 20480         // 4 planes x 64 x 80

// ---- smem byte offsets (per CTA) ----
#define SM_QH   0           // 64 x 272
#define SM_QL   17408
#define SM_K    34816       // single-buffered K tile
#define SM_V0   69632
#define SM_V1   90112
#define SM_TOTAL 110592

__device__ static __align__(16) unsigned char g_kpre[(size_t)NB * NTILES * KTILE];
__device__ static __align__(16) unsigned char g_vpre[(size_t)NB * NTILES * VTILE];

#define LDSM4(R, addr) \
    asm volatile("ldmatrix.sync.aligned.m8n8.x4.shared.b16 {%0,%1,%2,%3}, [%4];" \
        : "=r"((R)[0]), "=r"((R)[1]), "=r"((R)[2]), "=r"((R)[3]) : "r"(addr))

#define MMA(D, A, B0, B1) \
    asm volatile("mma.sync.aligned.m16n8k16.row.col.f32.bf16.bf16.f32 " \
        "{%0,%1,%2,%3}, {%4,%5,%6,%7}, {%8,%9}, {%0,%1,%2,%3};" \
        : "+f"((D)[0]), "+f"((D)[1]), "+f"((D)[2]), "+f"((D)[3]) \
        : "r"((A)[0]), "r"((A)[1]), "r"((A)[2]), "r"((A)[3]), "r"(B0), "r"(B1))

#define CP16(dst, src) \
    asm volatile("cp.async.cg.shared.global [%0], [%1], 16;" \
        :: "r"(dst), "l"(src) : "memory")
#define CP_COMMIT() asm volatile("cp.async.commit_group;" ::: "memory")
#define CP_WAIT0()  asm volatile("cp.async.wait_group 0;"  ::: "memory")

__device__ __forceinline__ u32 smem_u32(const void* p) {
    u32 a;
    asm("{ .reg .u64 t; cvta.to.shared.u64 t, %1; cvt.u32.u64 %0, t; }"
        : "=r"(a) : "l"(p));
    return a;
}
__device__ __forceinline__ void split2(float a, float b, u32& hp, u32& lp) {
    __nv_bfloat16 ha = __float2bfloat16(a), hb = __float2bfloat16(b);
    float la = a - __bfloat162float(ha), lb = b - __bfloat162float(hb);
    __nv_bfloat16 lA = __float2bfloat16(la), lB = __float2bfloat16(lb);
    hp = (u32)__bfloat16_as_ushort(ha) | ((u32)__bfloat16_as_ushort(hb) << 16);
    lp = (u32)__bfloat16_as_ushort(lA) | ((u32)__bfloat16_as_ushort(lB) << 16);
}
__device__ __forceinline__ void split4(float a, float b, float c, float d,
                                       u64& hp, u64& lp) {
    u32 h0, l0, h1, l1;
    split2(a, b, h0, l0);
    split2(c, d, h1, l1);
    hp = (u64)h0 | ((u64)h1 << 32);
    lp = (u64)l0 | ((u64)l1 << 32);
}

// ---- prep: K -> {KR=(Kr,Ki), KI=(Ki,-Kr)} hi/lo planes (rows=key, 128 interleaved d) ----
__global__ void prep_k_kernel(const float* __restrict__ gk) {
    int g = blockIdx.x * 8 + (threadIdx.x >> 5);    // global k-row (b*4096+krow)
    int lane = threadIdx.x & 31;
    int b = g >> 12, krow = g & 4095;
    int tile = krow >> 5, r = krow & 31;
    float4 v = ((const float4*)gk)[(size_t)g * 32 + lane];
    unsigned char* base = g_kpre + (size_t)(b * NTILES + tile) * KTILE
                        + r * PK + lane * 8;
    u64 hp, lp;
    split4(v.x, v.y, v.z, v.w, hp, lp);
    *(u64*)(base        ) = hp;
    *(u64*)(base +  8704) = lp;
    split4(v.y, -v.x, v.w, -v.z, hp, lp);
    *(u64*)(base + 17408) = hp;
    *(u64*)(base + 26112) = lp;
}

// ---- prep: V -> planar transposed {Vr, Vi} hi/lo planes (rows = v-col, cols = 32 keys) ----
__global__ void prep_v_kernel(const float* __restrict__ gv) {
    int bt = blockIdx.x;                            // b*128 + tile
    int b = bt >> 7, tile = bt & 127;
    int t = threadIdx.x;
    int v = t & 63;
    int kb = (t >> 6) * 8;                          // 0,8,16,24
    const float2* src = (const float2*)gv
        + ((size_t)(b * KLEN + tile * TK + kb) * VH + v);
    unsigned char* base = g_vpre + (size_t)bt * VTILE + v * PVR + kb * 2;
    u32 rh[4], rl[4], ih[4], il[4];
    #pragma unroll
    for (int j = 0; j < 4; ++j) {
        float2 x0 = src[(size_t)(2 * j) * VH];
        float2 x1 = src[(size_t)(2 * j + 1) * VH];
        split2(x0.x, x1.x, rh[j], rl[j]);
        split2(x0.y, x1.y, ih[j], il[j]);
    }
    *(uint4*)(base         ) = make_uint4(rh[0], rh[1], rh[2], rh[3]);
    *(uint4*)(base +  5120) = make_uint4(rl[0], rl[1], rl[2], rl[3]);
    *(uint4*)(base + 10240) = make_uint4(ih[0], ih[1], ih[2], ih[3]);
    *(uint4*)(base + 15360) = make_uint4(il[0], il[1], il[2], il[3]);
}

__device__ __forceinline__ void issue_k(u32 smb, int b, int t) {
    const unsigned char* src = g_kpre + (size_t)(b * NTILES + t) * KTILE;
    u32 dst = smb + SM_K;
    #pragma unroll 2
    for (int i = threadIdx.x; i < KTILE / 16; i += NT)
        CP16(dst + i * 16, src + (size_t)i * 16);
}
__device__ __forceinline__ void issue_v(u32 smb, int b, int t, int buf) {
    const unsigned char* src = g_vpre + (size_t)(b * NTILES + t) * VTILE;
    u32 dst = smb + SM_V0 + buf * VTILE;
    #pragma unroll 2
    for (int i = threadIdx.x; i < VTILE / 16; i += NT)
        CP16(dst + i * 16, src + (size_t)i * 16);
}

__global__ __launch_bounds__(NT, 2)
void cdpa_mma_kernel(const float* __restrict__ gq,
                     float* __restrict__ gout)
{
    extern __shared__ char sm[];
    const u32 smb = smem_u32(sm);
    const int tid = threadIdx.x;
    const int lane = tid & 31, wid = tid >> 5;      // 4 warps = 4 q-slices of 16
    const int g = lane >> 2, tg = lane & 3;
    const int b = blockIdx.y, q0 = blockIdx.x * TQ;

    // prologue: prefetch tile 0
    issue_k(smb, b, 0);
    issue_v(smb, b, 0, 0);
    CP_COMMIT();

    // ldmatrix lane addressing
    const int arow = lane & 15, akb = lane >> 4;
    const int bn = (lane & 7) + ((lane >> 4) << 3), bkb = (lane >> 3) & 1;

    const u32 aQH = smb + SM_QH + (u32)(16 * wid + arow) * PK + akb * 16;
    const u32 aQL = aQH + (SM_QL - SM_QH);
    const u32 kfo = (u32)bn * PK + bkb * 16;        // + plane + nblk*16*PK + ks*32
    const u32 vfo = (u32)bn * PVR + bkb * 16;       // + plane + nblk*16*PVR + 32*c

    // ---- Q tile: scale 1/8, bf16 hi/lo split ----
    {
        const float4* gqp = (const float4*)gq + (size_t)(b * QLEN + q0) * 32;
        #pragma unroll 4
        for (int it = 0; it < 16; ++it) {
            int e = it * NT + tid;
            int row = e >> 5, c4 = e & 31;
            float4 v = gqp[e];
            v.x *= 0.125f; v.y *= 0.125f; v.z *= 0.125f; v.w *= 0.125f;
            u64 hp, lp;
            split4(v.x, v.y, v.z, v.w, hp, lp);
            u32 off = (u32)row * PK + c4 * 8;
            *(u64*)(sm + SM_QH + off) = hp;
            *(u64*)(sm + SM_QL + off) = lp;
        }
    }

    float yr[8][4], yi[8][4], Zp[2];
    Zp[0] = 0.0f; Zp[1] = 0.0f;
    #pragma unroll
    for (int nf = 0; nf < 8; ++nf)
        #pragma unroll
        for (int e = 0; e < 4; ++e) { yr[nf][e] = 0.0f; yi[nf][e] = 0.0f; }

    for (int t = 0; t < NTILES; ++t) {
        CP_WAIT0();
        __syncthreads();        // K[t],V[t] visible; AV[t-1] reads done

        // prefetch V[t+1] into the alternate buffer (whole-tile flight)
        if (t + 1 < NTILES) {
            issue_v(smb, b, t + 1, (t + 1) & 1);
            CP_COMMIT();
        }
        const u32 kb = smb + SM_K;
        const u32 vb = smb + SM_V0 + (u32)(t & 1) * VTILE;

        // ---- S gemm: 16q x 32 keys, interleaved complex K=128, 3-term split ----
        float sr[4][4], si[4][4];
        #pragma unroll
        for (int nf = 0; nf < 4; ++nf)
            #pragma unroll
            for (int e = 0; e < 4; ++e) { sr[nf][e] = 0.0f; si[nf][e] = 0.0f; }

        #pragma unroll
        for (int ks = 0; ks < 8; ++ks) {
            const u32 ko = ks * 32;
            u32 qh[4], ql[4];
            LDSM4(qh, aQH + ko);
            LDSM4(ql, aQL + ko);
            #pragma unroll
            for (int nblk = 0; nblk < 2; ++nblk) {
                const u32 base = kb + kfo + (u32)nblk * (16 * PK) + ko;
                u32 rh[4], rl[4], ih2[4], il2[4];
                LDSM4(rh, base);           LDSM4(rl, base + 8704);
                LDSM4(ih2, base + 17408);  LDSM4(il2, base + 26112);
                #pragma unroll
                for (int h = 0; h < 2; ++h) {
                    const int nf = 2 * nblk + h;
                    MMA(sr[nf], qh, rh[2*h], rh[2*h+1]);
                    MMA(sr[nf], qh, rl[2*h], rl[2*h+1]);
                    MMA(sr[nf], ql, rh[2*h], rh[2*h+1]);
                    MMA(si[nf], qh, ih2[2*h], ih2[2*h+1]);
                    MMA(si[nf], qh, il2[2*h], il2[2*h+1]);
                    MMA(si[nf], ql, ih2[2*h], ih2[2*h+1]);
                }
            }
        }

        __syncthreads();        // all warps done reading K[t]
        if (t + 1 < NTILES) {
            issue_k(smb, b, t + 1);     // overwrite K buffer; lands by next CP_WAIT0
            CP_COMMIT();
        }

        // ---- epilogue in registers: n=|S|, e=exp(n), A=S*e/n ----
        #pragma unroll
        for (int nf = 0; nf < 4; ++nf) {
            #pragma unroll
            for (int e = 0; e < 4; ++e) {
                float a = sr[nf][e];
                float bb = si[nf][e];
                float s2 = a * a + bb * bb;
                float r = rsqrtf(s2);
                float n = s2 * r;
                float ee = __expf(n);
                float w = ee * r;
                if (s2 < 1e-30f) { w = 0.0f; ee = 1.0f; }
                Zp[e >> 1] += ee;
                sr[nf][e] = a * w;      // Ar
                si[nf][e] = bb * w;     // Ai
            }
        }

        // ---- AV gemm: planar, A frags packed from registers (no smem) ----
        #pragma unroll
        for (int c = 0; c < 2; ++c) {   // key chunks of 16
            u32 ArH[4], ArL[4], AiH[4], AiL[4], AnH[4], AnL[4];
            split2(sr[2*c][0],   sr[2*c][1],   ArH[0], ArL[0]);
            split2(sr[2*c][2],   sr[2*c][3],   ArH[1], ArL[1]);
            split2(sr[2*c+1][0], sr[2*c+1][1], ArH[2], ArL[2]);
            split2(sr[2*c+1][2], sr[2*c+1][3], ArH[3], ArL[3]);
            split2(si[2*c][0],   si[2*c][1],   AiH[0], AiL[0]);
            split2(si[2*c][2],   si[2*c][3],   AiH[1], AiL[1]);
            split2(si[2*c+1][0], si[2*c+1][1], AiH[2], AiL[2]);
            split2(si[2*c+1][2], si[2*c+1][3], AiH[3], AiL[3]);
            #pragma unroll
            for (int j = 0; j < 4; ++j) {
                AnH[j] = AiH[j] ^ 0x80008000u;   // -Ai (exact bf16 sign flip)
                AnL[j] = AiL[j] ^ 0x80008000u;
            }

            u32 vh[16], vl[16];
            // Vr planes
            #pragma unroll
            for (int nblk = 0; nblk < 4; ++nblk) {
                const u32 o2 = vfo + (u32)nblk * (16 * PVR) + 32 * c;
                LDSM4(vh + 4 * nblk, vb + o2);
                LDSM4(vl + 4 * nblk, vb + 5120 + o2);
            }
            #pragma unroll
            for (int nf = 0; nf < 8; ++nf) {
                MMA(yr[nf], ArH, vh[2*nf], vh[2*nf+1]);
                MMA(yr[nf], ArH, vl[2*nf], vl[2*nf+1]);
                MMA(yr[nf], ArL, vh[2*nf], vh[2*nf+1]);
                MMA(yi[nf], AiH, vh[2*nf], vh[2*nf+1]);
                MMA(yi[nf], AiH, vl[2*nf], vl[2*nf+1]);
                MMA(yi[nf], AiL, vh[2*nf], vh[2*nf+1]);
            }
            // Vi planes
            #pragma unroll
            for (int nblk = 0; nblk < 4; ++nblk) {
                const u32 o2 = vfo + (u32)nblk * (16 * PVR) + 32 * c;
                LDSM4(vh + 4 * nblk, vb + 10240 + o2);
                LDSM4(vl + 4 * nblk, vb + 15360 + o2);
            }
            #pragma unroll
            for (int nf = 0; nf < 8; ++nf) {
                MMA(yi[nf], ArH, vh[2*nf], vh[2*nf+1]);
                MMA(yi[nf], ArH, vl[2*nf], vl[2*nf+1]);
                MMA(yi[nf], ArL, vh[2*nf], vh[2*nf+1]);
                MMA(yr[nf], AnH, vh[2*nf], vh[2*nf+1]);
                MMA(yr[nf], AnH, vl[2*nf], vl[2*nf+1]);
                MMA(yr[nf], AnL, vh[2*nf], vh[2*nf+1]);
            }
        }
    }

    // ---- Z reduce within quad (keys live across tg lanes) ----
    #pragma unroll
    for (int rr = 0; rr < 2; ++rr) {
        float z = Zp[rr];
        z += __shfl_xor_sync(0xffffffffu, z, 1);
        z += __shfl_xor_sync(0xffffffffu, z, 2);
        Zp[rr] = z;
    }

    // ---- output: Y / Z -> [B, Q, V, 2] ----
    #pragma unroll
    for (int rr = 0; rr < 2; ++rr) {
        const float inv = 1.0f / Zp[rr];
        const int qrow = q0 + 16 * wid + g + 8 * rr;
        float2* o = (float2*)gout + (size_t)(b * QLEN + qrow) * VH;
        #pragma unroll
        for (int nf = 0; nf < 8; ++nf) {
            #pragma unroll
            for (int cc = 0; cc < 2; ++cc) {
                const int v = 8 * nf + 2 * tg + cc;
                o[v] = make_float2(yr[nf][2 * rr + cc] * inv,
                                   yi[nf][2 * rr + cc] * inv);
            }
        }
    }
}

extern "C" void kernel_launch(void* const* d_in, const int* in_sizes, int n_in,
                              void* d_out, int out_size)
{
    const float* q = (const float*)d_in[0];
    const float* k = (const float*)d_in[1];
    const float* v = (const float*)d_in[2];
    float* out = (float*)d_out;

    prep_k_kernel<<<2048, 256>>>(k);
    prep_v_kernel<<<512, 256>>>(v);

    cudaFuncSetAttribute(cdpa_mma_kernel,
                         cudaFuncAttributeMaxDynamicSharedMemorySize, SM_TOTAL);
    dim3 grid(QLEN / TQ, NB);
    cdpa_mma_kernel<<<grid, NT, SM_TOTAL>>>(q, out);
}